// round 16
// baseline (speedup 1.0000x reference)
#include <cuda_runtime.h>

#define NN 100000
#define NE 1600000
#define F_IN 64
#define F_HID 64
#define F_OUT 32

// ---- scratch (device globals; no allocation allowed) ----
__device__ float g_h1  [NN * F_HID];   // (x@W1)*outnorm
__device__ float g_agg1[NN * F_HID];
__device__ float g_h2  [NN * F_OUT];
__device__ float g_outnorm[NN];
__device__ float g_innorm [NN];
__device__ int   g_degs[NN];
__device__ int   g_degd[NN];
__device__ int   g_rowptr[NN];
__device__ int   g_rowend[NN];
__device__ int   g_eloc[NE];           // per-edge within-row ordinal (from k_deg4)
__device__ int   g_csr_src[NE];
__device__ int   g_total;

// ---- zero degree counters + edge-space counter ----
__global__ void k_zero() {
    int i = blockIdx.x * blockDim.x + threadIdx.x;
    if (i < NN) { g_degs[i] = 0; g_degd[i] = 0; }
    if (i == 0) g_total = 0;
}

// ---- degrees: 4 edges/thread; dst atomics return the edge's row ordinal ----
__global__ void k_deg4(const int* __restrict__ src, const int* __restrict__ dst) {
    int t = blockIdx.x * blockDim.x + threadIdx.x;
    if (t >= NE / 4) return;
    int4 s = reinterpret_cast<const int4*>(src)[t];
    int4 d = reinterpret_cast<const int4*>(dst)[t];
    atomicAdd(&g_degs[s.x], 1);
    atomicAdd(&g_degs[s.y], 1);
    atomicAdd(&g_degs[s.z], 1);
    atomicAdd(&g_degs[s.w], 1);
    int4 l;
    l.x = atomicAdd(&g_degd[d.x], 1);
    l.y = atomicAdd(&g_degd[d.y], 1);
    l.z = atomicAdd(&g_degd[d.z], 1);
    l.w = atomicAdd(&g_degd[d.w], 1);
    reinterpret_cast<int4*>(g_eloc)[t] = l;
}

// ---- single-kernel range allocation + norms ----
__global__ __launch_bounds__(256) void k_scanalloc() {
    __shared__ int wsum[8];
    __shared__ int sbase;
    int t = threadIdx.x;
    int i = blockIdx.x * 256 + t;
    int d = (i < NN) ? g_degd[i] : 0;

    int lane = t & 31, wid = t >> 5;
    int x = d;
    #pragma unroll
    for (int o = 1; o < 32; o <<= 1) {
        int y = __shfl_up_sync(0xffffffffu, x, o);
        if (lane >= o) x += y;
    }
    if (lane == 31) wsum[wid] = x;
    __syncthreads();
    if (wid == 0 && lane < 8) {
        int w = wsum[lane];
        #pragma unroll
        for (int o = 1; o < 8; o <<= 1) {
            int y = __shfl_up_sync(0x000000ffu, w, o);
            if (lane >= o) w += y;
        }
        wsum[lane] = w;
    }
    __syncthreads();
    if (t == 0) sbase = atomicAdd(&g_total, wsum[7]);
    int incl = x + (wid > 0 ? wsum[wid - 1] : 0);
    int excl = incl - d;
    __syncthreads();

    if (i < NN) {
        int r = sbase + excl;
        g_rowptr[i] = r;
        g_rowend[i] = r + d;
        int ds = g_degs[i]; if (ds < 1) ds = 1;
        int dd = d;         if (dd < 1) dd = 1;
        g_outnorm[i] = rsqrtf((float)ds);
        g_innorm[i]  = rsqrtf((float)dd);
    }
}

// ---- scatter: atomic-free CSR fill using precomputed ordinals ----
__global__ void k_scatter4(const int* __restrict__ src, const int* __restrict__ dst) {
    int t = blockIdx.x * blockDim.x + threadIdx.x;
    if (t >= NE / 4) return;
    int4 s = reinterpret_cast<const int4*>(src)[t];
    int4 d = reinterpret_cast<const int4*>(dst)[t];
    int4 l = reinterpret_cast<const int4*>(g_eloc)[t];
    int r0 = __ldg(&g_rowptr[d.x]);
    int r1 = __ldg(&g_rowptr[d.y]);
    int r2 = __ldg(&g_rowptr[d.z]);
    int r3 = __ldg(&g_rowptr[d.w]);
    g_csr_src[r0 + l.x] = s.x;
    g_csr_src[r1 + l.y] = s.y;
    g_csr_src[r2 + l.z] = s.z;
    g_csr_src[r3 + l.w] = s.w;
}

// ---- GEMM1: h1 = (x @ W1) * outnorm.  128-node tile, 128 thr, 8x8/thread. ----
__global__ __launch_bounds__(128) void k_gemm1(const float* __restrict__ x,
                                               const float* __restrict__ W1) {
    __shared__ float Ws[64 * 64];      // 16 KB
    __shared__ float xs[64][128];      // 32 KB
    int tid = threadIdx.x;
    int nb  = blockIdx.x * 128;

    #pragma unroll
    for (int r = 0; r < 8; r++) {
        int idx = tid + r * 128;
        reinterpret_cast<float4*>(Ws)[idx] =
            reinterpret_cast<const float4*>(W1)[idx];
    }
    {
        int node = nb + tid;
        bool ok = node < NN;
        #pragma unroll
        for (int k4 = 0; k4 < 16; k4++) {
            float4 v = make_float4(0.f, 0.f, 0.f, 0.f);
            if (ok) v = reinterpret_cast<const float4*>(x)[node * 16 + k4];
            xs[k4 * 4 + 0][tid] = v.x;
            xs[k4 * 4 + 1][tid] = v.y;
            xs[k4 * 4 + 2][tid] = v.z;
            xs[k4 * 4 + 3][tid] = v.w;
        }
    }
    __syncthreads();

    int tx = tid & 7;
    int ty = tid >> 3;
    int j0 = tx * 8, n0 = ty * 8;
    float acc[8][8] = {};
    #pragma unroll
    for (int k = 0; k < 64; k++) {
        float4 wa = *reinterpret_cast<const float4*>(&Ws[k * 64 + j0]);
        float4 wb = *reinterpret_cast<const float4*>(&Ws[k * 64 + j0 + 4]);
        float4 xa = *reinterpret_cast<const float4*>(&xs[k][n0]);
        float4 xb = *reinterpret_cast<const float4*>(&xs[k][n0 + 4]);
        float wr[8] = {wa.x, wa.y, wa.z, wa.w, wb.x, wb.y, wb.z, wb.w};
        float xr[8] = {xa.x, xa.y, xa.z, xa.w, xb.x, xb.y, xb.z, xb.w};
        #pragma unroll
        for (int i = 0; i < 8; i++)
            #pragma unroll
            for (int j = 0; j < 8; j++)
                acc[i][j] += xr[i] * wr[j];
    }
    #pragma unroll
    for (int i = 0; i < 8; i++) {
        int node = nb + n0 + i;
        if (node < NN) {
            float s = g_outnorm[node];
            float4 o0 = make_float4(acc[i][0] * s, acc[i][1] * s,
                                    acc[i][2] * s, acc[i][3] * s);
            float4 o1 = make_float4(acc[i][4] * s, acc[i][5] * s,
                                    acc[i][6] * s, acc[i][7] * s);
            reinterpret_cast<float4*>(g_h1)[node * 16 + tx * 2 + 0] = o0;
            reinterpret_cast<float4*>(g_h1)[node * 16 + tx * 2 + 1] = o1;
        }
    }
}

// ---- gather1: agg1[n] = sum_s h1[s].  Half-warp per node, float4 loads. ----
__global__ __launch_bounds__(256) void k_gather1() {
    int gw = (blockIdx.x * 256 + threadIdx.x) >> 5;
    int lane = threadIdx.x & 31;
    int half = lane >> 4, hl = lane & 15;
    int node = gw * 2 + half;
    if (node >= NN) return;
    unsigned hmask = 0xFFFFu << (half * 16);
    int beg = g_rowptr[node], end = g_rowend[node];

    float4 a0 = make_float4(0.f,0.f,0.f,0.f), a1 = a0, a2 = a0, a3 = a0;
    for (int c = beg; c < end; c += 16) {
        int idx = c + hl;
        int sreg = (idx < end) ? g_csr_src[idx] : 0;
        int n = end - c; if (n > 16) n = 16;
        int j = 0;
        for (; j + 4 <= n; j += 4) {
            int s0 = __shfl_sync(hmask, sreg, j + 0, 16);
            int s1 = __shfl_sync(hmask, sreg, j + 1, 16);
            int s2 = __shfl_sync(hmask, sreg, j + 2, 16);
            int s3 = __shfl_sync(hmask, sreg, j + 3, 16);
            float4 v0 = reinterpret_cast<const float4*>(g_h1)[s0 * 16 + hl];
            float4 v1 = reinterpret_cast<const float4*>(g_h1)[s1 * 16 + hl];
            float4 v2 = reinterpret_cast<const float4*>(g_h1)[s2 * 16 + hl];
            float4 v3 = reinterpret_cast<const float4*>(g_h1)[s3 * 16 + hl];
            a0.x += v0.x; a0.y += v0.y; a0.z += v0.z; a0.w += v0.w;
            a1.x += v1.x; a1.y += v1.y; a1.z += v1.z; a1.w += v1.w;
            a2.x += v2.x; a2.y += v2.y; a2.z += v2.z; a2.w += v2.w;
            a3.x += v3.x; a3.y += v3.y; a3.z += v3.z; a3.w += v3.w;
        }
        for (; j < n; j++) {
            int s = __shfl_sync(hmask, sreg, j, 16);
            float4 v = reinterpret_cast<const float4*>(g_h1)[s * 16 + hl];
            a0.x += v.x; a0.y += v.y; a0.z += v.z; a0.w += v.w;
        }
    }
    float4 r;
    r.x = (a0.x + a1.x) + (a2.x + a3.x);
    r.y = (a0.y + a1.y) + (a2.y + a3.y);
    r.z = (a0.z + a1.z) + (a2.z + a3.z);
    r.w = (a0.w + a1.w) + (a2.w + a3.w);
    reinterpret_cast<float4*>(g_agg1)[node * 16 + hl] = r;
}

// ---- Fused layer-1 epilogue + GEMM2 (64 -> 32) ----
__global__ __launch_bounds__(256) void k_gemm2(const float* __restrict__ W2,
                                               const float* __restrict__ b1) {
    __shared__ float Ws[64 * 32];
    __shared__ float xs[64][68];
    int tid = threadIdx.x;
    int nb  = blockIdx.x * 64;

    #pragma unroll
    for (int r = 0; r < 2; r++) {
        int idx = tid + r * 256;
        reinterpret_cast<float4*>(Ws)[idx] =
            reinterpret_cast<const float4*>(W2)[idx];
    }
    #pragma unroll
    for (int r = 0; r < 4; r++) {
        int idx = tid + r * 256;
        int n = idx >> 4, k4 = idx & 15;
        int node = nb + n;
        float4 v = make_float4(0.f, 0.f, 0.f, 0.f);
        if (node < NN) {
            v = reinterpret_cast<const float4*>(g_agg1)[node * 16 + k4];
            float in_n = g_innorm[node];
            float on   = g_outnorm[node];
            float4 bb  = reinterpret_cast<const float4*>(b1)[k4];
            v.x = fmaxf(fmaf(v.x, in_n, bb.x), 0.f) * on;
            v.y = fmaxf(fmaf(v.y, in_n, bb.y), 0.f) * on;
            v.z = fmaxf(fmaf(v.z, in_n, bb.z), 0.f) * on;
            v.w = fmaxf(fmaf(v.w, in_n, bb.w), 0.f) * on;
        }
        xs[k4 * 4 + 0][n] = v.x;
        xs[k4 * 4 + 1][n] = v.y;
        xs[k4 * 4 + 2][n] = v.z;
        xs[k4 * 4 + 3][n] = v.w;
    }
    __syncthreads();

    int tx = tid & 7;
    int ty = tid >> 3;
    float acc[2][4] = {};
    #pragma unroll
    for (int k = 0; k < 64; k++) {
        float4 wv = *reinterpret_cast<const float4*>(&Ws[k * 32 + tx * 4]);
        float x0 = xs[k][ty * 2 + 0];
        float x1 = xs[k][ty * 2 + 1];
        acc[0][0] += x0 * wv.x; acc[0][1] += x0 * wv.y;
        acc[0][2] += x0 * wv.z; acc[0][3] += x0 * wv.w;
        acc[1][0] += x1 * wv.x; acc[1][1] += x1 * wv.y;
        acc[1][2] += x1 * wv.z; acc[1][3] += x1 * wv.w;
    }
    #pragma unroll
    for (int i = 0; i < 2; i++) {
        int node = nb + ty * 2 + i;
        if (node < NN) {
            float4 o = make_float4(acc[i][0], acc[i][1], acc[i][2], acc[i][3]);
            reinterpret_cast<float4*>(g_h2)[node * 8 + tx] = o;
        }
    }
}

// ---- gather2 + final epilogue. Quarter-warp per node, float4 loads. ----
__global__ __launch_bounds__(256) void k_gather2(const float* __restrict__ b2,
                                                 float* __restrict__ out) {
    int gw = (blockIdx.x * 256 + threadIdx.x) >> 5;
    int lane = threadIdx.x & 31;
    int q = lane >> 3, ql = lane & 7;
    int node = gw * 4 + q;
    if (node >= NN) return;
    unsigned qmask = 0xFFu << (q * 8);
    int beg = g_rowptr[node], end = g_rowend[node];

    float4 a0 = make_float4(0.f,0.f,0.f,0.f), a1 = a0, a2 = a0, a3 = a0;
    for (int c = beg; c < end; c += 8) {
        int idx = c + ql;
        int sreg = (idx < end) ? g_csr_src[idx] : 0;
        int n = end - c; if (n > 8) n = 8;
        int j = 0;
        for (; j + 4 <= n; j += 4) {
            int s0 = __shfl_sync(qmask, sreg, j + 0, 8);
            int s1 = __shfl_sync(qmask, sreg, j + 1, 8);
            int s2 = __shfl_sync(qmask, sreg, j + 2, 8);
            int s3 = __shfl_sync(qmask, sreg, j + 3, 8);
            float4 v0 = reinterpret_cast<const float4*>(g_h2)[s0 * 8 + ql];
            float4 v1 = reinterpret_cast<const float4*>(g_h2)[s1 * 8 + ql];
            float4 v2 = reinterpret_cast<const float4*>(g_h2)[s2 * 8 + ql];
            float4 v3 = reinterpret_cast<const float4*>(g_h2)[s3 * 8 + ql];
            a0.x += v0.x; a0.y += v0.y; a0.z += v0.z; a0.w += v0.w;
            a1.x += v1.x; a1.y += v1.y; a1.z += v1.z; a1.w += v1.w;
            a2.x += v2.x; a2.y += v2.y; a2.z += v2.z; a2.w += v2.w;
            a3.x += v3.x; a3.y += v3.y; a3.z += v3.z; a3.w += v3.w;
        }
        for (; j < n; j++) {
            int s = __shfl_sync(qmask, sreg, j, 8);
            float4 v = reinterpret_cast<const float4*>(g_h2)[s * 8 + ql];
            a0.x += v.x; a0.y += v.y; a0.z += v.z; a0.w += v.w;
        }
    }
    float4 r;
    r.x = (a0.x + a1.x) + (a2.x + a3.x);
    r.y = (a0.y + a1.y) + (a2.y + a3.y);
    r.z = (a0.z + a1.z) + (a2.z + a3.z);
    r.w = (a0.w + a1.w) + (a2.w + a3.w);
    float inr = g_innorm[node];
    float4 bb = reinterpret_cast<const float4*>(b2)[ql];
    float4 o;
    o.x = fmaf(r.x, inr, bb.x);
    o.y = fmaf(r.y, inr, bb.y);
    o.z = fmaf(r.z, inr, bb.z);
    o.w = fmaf(r.w, inr, bb.w);
    reinterpret_cast<float4*>(out)[node * 8 + ql] = o;
}

extern "C" void kernel_launch(void* const* d_in, const int* in_sizes, int n_in,
                              void* d_out, int out_size) {
    const float* x   = (const float*)d_in[0];
    const int*   src = (const int*)  d_in[1];
    const int*   dst = (const int*)  d_in[2];
    const float* W1  = (const float*)d_in[3];
    const float* b1  = (const float*)d_in[4];
    const float* W2  = (const float*)d_in[5];
    const float* b2  = (const float*)d_in[6];
    float* out = (float*)d_out;

    const int T = 256;
    k_zero     <<<(NN + T - 1) / T, T>>>();
    k_deg4     <<<(NE / 4 + T - 1) / T, T>>>(src, dst);
    k_scanalloc<<<(NN + 255) / 256, 256>>>();
    k_scatter4 <<<(NE / 4 + T - 1) / T, T>>>(src, dst);
    k_gemm1    <<<(NN + 127) / 128, 128>>>(x, W1);
    k_gather1  <<<(NN / 2 * 32 + 255) / 256, 256>>>();
    k_gemm2    <<<(NN + 63) / 64, 256>>>(W2, b1);
    k_gather2  <<<(NN / 4 * 32 + 255) / 256, 256>>>(b2, out);
}

// round 17
// speedup vs baseline: 1.0960x; 1.0960x over previous
#include <cuda_runtime.h>

#define NN 100000
#define NE 1600000
#define F_IN 64
#define F_HID 64
#define F_OUT 32

#define NBLK_DEG  1563               // ceil(NE/4/256): 1024 edges per block
#define NBLK_GEMM 782                // ceil(NN/128)
#define NBLK_FUSED 2346              // gemm blocks at bid%3==2 (782), deg gets 1564 slots

// ---- scratch (device globals; no allocation allowed) ----
__device__ float g_h1  [NN * F_HID];   // x@W1 (unscaled; outnorm applied in gather1)
__device__ float g_agg1[NN * F_HID];
__device__ float g_h2  [NN * F_OUT];
__device__ float g_outnorm[NN];
__device__ float g_innorm [NN];
__device__ int   g_degs[NN];
__device__ int   g_degd[NN];
__device__ int   g_rowptr[NN];
__device__ int   g_rowend[NN];
__device__ int   g_eloc[NE];
__device__ int   g_csr_src[NE];
__device__ int   g_total;

// ---- zero degree counters + edge-space counter ----
__global__ void k_zero() {
    int i = blockIdx.x * blockDim.x + threadIdx.x;
    if (i < NN) { g_degs[i] = 0; g_degd[i] = 0; }
    if (i == 0) g_total = 0;
}

// ---- FUSED: degree histogram (deg blocks) + GEMM1 (gemm blocks), one launch.
//      gemm blocks: h1 = x @ W1, 128-node tile, 256 thr, 8x4/thread. ----
__global__ __launch_bounds__(256) void k_deg_gemm(const int* __restrict__ src,
                                                  const int* __restrict__ dst,
                                                  const float* __restrict__ x,
                                                  const float* __restrict__ W1) {
    __shared__ float Ws[64 * 64];      // 16 KB
    __shared__ float xs[64][128];      // 32 KB (48 KB total)
    int tid = threadIdx.x;
    int bid = blockIdx.x;

    if (bid % 3 != 2) {
        // ---- degree branch ----
        int deg_bid = bid - (bid + 1) / 3;
        if (deg_bid >= NBLK_DEG) return;
        int t = deg_bid * 256 + tid;
        if (t >= NE / 4) return;
        int4 s = reinterpret_cast<const int4*>(src)[t];
        int4 d = reinterpret_cast<const int4*>(dst)[t];
        atomicAdd(&g_degs[s.x], 1);
        atomicAdd(&g_degs[s.y], 1);
        atomicAdd(&g_degs[s.z], 1);
        atomicAdd(&g_degs[s.w], 1);
        int4 l;
        l.x = atomicAdd(&g_degd[d.x], 1);
        l.y = atomicAdd(&g_degd[d.y], 1);
        l.z = atomicAdd(&g_degd[d.z], 1);
        l.w = atomicAdd(&g_degd[d.w], 1);
        reinterpret_cast<int4*>(g_eloc)[t] = l;
        return;
    }

    // ---- gemm branch ----
    int nb = (bid / 3) * 128;

    #pragma unroll
    for (int r = 0; r < 4; r++) {
        int idx = tid + r * 256;
        reinterpret_cast<float4*>(Ws)[idx] =
            reinterpret_cast<const float4*>(W1)[idx];
    }
    // Stage x: 2 threads per node, each covers 8 float4 of the row.
    {
        int n    = tid >> 1;            // 0..127
        int half = tid & 1;             // 0..1
        int node = nb + n;
        bool ok = node < NN;
        #pragma unroll
        for (int i = 0; i < 8; i++) {
            int k4 = half * 8 + i;
            float4 v = make_float4(0.f, 0.f, 0.f, 0.f);
            if (ok) v = reinterpret_cast<const float4*>(x)[node * 16 + k4];
            xs[k4 * 4 + 0][n] = v.x;
            xs[k4 * 4 + 1][n] = v.y;
            xs[k4 * 4 + 2][n] = v.z;
            xs[k4 * 4 + 3][n] = v.w;
        }
    }
    __syncthreads();

    int tx = tid & 15;       // j0 = tx*4
    int ty = tid >> 4;       // n0 = ty*8
    int j0 = tx * 4, n0 = ty * 8;
    float acc[8][4] = {};
    #pragma unroll
    for (int k = 0; k < 64; k++) {
        float4 wv = *reinterpret_cast<const float4*>(&Ws[k * 64 + j0]);
        float4 xa = *reinterpret_cast<const float4*>(&xs[k][n0]);
        float4 xb = *reinterpret_cast<const float4*>(&xs[k][n0 + 4]);
        float xr[8] = {xa.x, xa.y, xa.z, xa.w, xb.x, xb.y, xb.z, xb.w};
        #pragma unroll
        for (int i = 0; i < 8; i++) {
            acc[i][0] += xr[i] * wv.x;
            acc[i][1] += xr[i] * wv.y;
            acc[i][2] += xr[i] * wv.z;
            acc[i][3] += xr[i] * wv.w;
        }
    }
    #pragma unroll
    for (int i = 0; i < 8; i++) {
        int node = nb + n0 + i;
        if (node < NN) {
            float4 o = make_float4(acc[i][0], acc[i][1], acc[i][2], acc[i][3]);
            reinterpret_cast<float4*>(g_h1)[node * 16 + tx] = o;
        }
    }
}

// ---- single-kernel range allocation + norms ----
__global__ __launch_bounds__(256) void k_scanalloc() {
    __shared__ int wsum[8];
    __shared__ int sbase;
    int t = threadIdx.x;
    int i = blockIdx.x * 256 + t;
    int d = (i < NN) ? g_degd[i] : 0;

    int lane = t & 31, wid = t >> 5;
    int x = d;
    #pragma unroll
    for (int o = 1; o < 32; o <<= 1) {
        int y = __shfl_up_sync(0xffffffffu, x, o);
        if (lane >= o) x += y;
    }
    if (lane == 31) wsum[wid] = x;
    __syncthreads();
    if (wid == 0 && lane < 8) {
        int w = wsum[lane];
        #pragma unroll
        for (int o = 1; o < 8; o <<= 1) {
            int y = __shfl_up_sync(0x000000ffu, w, o);
            if (lane >= o) w += y;
        }
        wsum[lane] = w;
    }
    __syncthreads();
    if (t == 0) sbase = atomicAdd(&g_total, wsum[7]);
    int incl = x + (wid > 0 ? wsum[wid - 1] : 0);
    int excl = incl - d;
    __syncthreads();

    if (i < NN) {
        int r = sbase + excl;
        g_rowptr[i] = r;
        g_rowend[i] = r + d;
        int ds = g_degs[i]; if (ds < 1) ds = 1;
        int dd = d;         if (dd < 1) dd = 1;
        g_outnorm[i] = rsqrtf((float)ds);
        g_innorm[i]  = rsqrtf((float)dd);
    }
}

// ---- scatter: atomic-free CSR fill using precomputed ordinals ----
__global__ void k_scatter4(const int* __restrict__ src, const int* __restrict__ dst) {
    int t = blockIdx.x * blockDim.x + threadIdx.x;
    if (t >= NE / 4) return;
    int4 s = reinterpret_cast<const int4*>(src)[t];
    int4 d = reinterpret_cast<const int4*>(dst)[t];
    int4 l = reinterpret_cast<const int4*>(g_eloc)[t];
    int r0 = __ldg(&g_rowptr[d.x]);
    int r1 = __ldg(&g_rowptr[d.y]);
    int r2 = __ldg(&g_rowptr[d.z]);
    int r3 = __ldg(&g_rowptr[d.w]);
    g_csr_src[r0 + l.x] = s.x;
    g_csr_src[r1 + l.y] = s.y;
    g_csr_src[r2 + l.z] = s.z;
    g_csr_src[r3 + l.w] = s.w;
}

// ---- gather1: agg1[n] = sum_s h1[s]*outnorm[s].  Warp/node, float2 + snorm fma. ----
__global__ __launch_bounds__(256) void k_gather1() {
    int w = (blockIdx.x * blockDim.x + threadIdx.x) >> 5;
    int lane = threadIdx.x & 31;
    if (w >= NN) return;
    int beg = g_rowptr[w], end = g_rowend[w];

    float2 a0 = {0.f, 0.f}, a1 = a0, a2 = a0, a3 = a0;
    for (int c = beg; c < end; c += 32) {
        int idx = c + lane;
        int sreg = 0; float snorm = 0.f;
        if (idx < end) { sreg = g_csr_src[idx]; snorm = g_outnorm[sreg]; }
        int n = end - c; if (n > 32) n = 32;
        int j = 0;
        for (; j + 4 <= n; j += 4) {
            int   s0 = __shfl_sync(0xffffffffu, sreg,  j + 0);
            int   s1 = __shfl_sync(0xffffffffu, sreg,  j + 1);
            int   s2 = __shfl_sync(0xffffffffu, sreg,  j + 2);
            int   s3 = __shfl_sync(0xffffffffu, sreg,  j + 3);
            float o0 = __shfl_sync(0xffffffffu, snorm, j + 0);
            float o1 = __shfl_sync(0xffffffffu, snorm, j + 1);
            float o2 = __shfl_sync(0xffffffffu, snorm, j + 2);
            float o3 = __shfl_sync(0xffffffffu, snorm, j + 3);
            float2 v0 = *reinterpret_cast<const float2*>(&g_h1[s0 * 64 + lane * 2]);
            float2 v1 = *reinterpret_cast<const float2*>(&g_h1[s1 * 64 + lane * 2]);
            float2 v2 = *reinterpret_cast<const float2*>(&g_h1[s2 * 64 + lane * 2]);
            float2 v3 = *reinterpret_cast<const float2*>(&g_h1[s3 * 64 + lane * 2]);
            a0.x = fmaf(v0.x, o0, a0.x); a0.y = fmaf(v0.y, o0, a0.y);
            a1.x = fmaf(v1.x, o1, a1.x); a1.y = fmaf(v1.y, o1, a1.y);
            a2.x = fmaf(v2.x, o2, a2.x); a2.y = fmaf(v2.y, o2, a2.y);
            a3.x = fmaf(v3.x, o3, a3.x); a3.y = fmaf(v3.y, o3, a3.y);
        }
        for (; j < n; j++) {
            int   s = __shfl_sync(0xffffffffu, sreg,  j);
            float o = __shfl_sync(0xffffffffu, snorm, j);
            float2 v = *reinterpret_cast<const float2*>(&g_h1[s * 64 + lane * 2]);
            a0.x = fmaf(v.x, o, a0.x); a0.y = fmaf(v.y, o, a0.y);
        }
    }
    float2 r;
    r.x = (a0.x + a1.x) + (a2.x + a3.x);
    r.y = (a0.y + a1.y) + (a2.y + a3.y);
    reinterpret_cast<float2*>(g_agg1)[w * 32 + lane] = r;
}

// ---- Fused layer-1 epilogue + GEMM2 (64 -> 32) ----
__global__ __launch_bounds__(256) void k_gemm2(const float* __restrict__ W2,
                                               const float* __restrict__ b1) {
    __shared__ float Ws[64 * 32];
    __shared__ float xs[64][68];
    int tid = threadIdx.x;
    int nb  = blockIdx.x * 64;

    #pragma unroll
    for (int r = 0; r < 2; r++) {
        int idx = tid + r * 256;
        reinterpret_cast<float4*>(Ws)[idx] =
            reinterpret_cast<const float4*>(W2)[idx];
    }
    #pragma unroll
    for (int r = 0; r < 4; r++) {
        int idx = tid + r * 256;
        int n = idx >> 4, k4 = idx & 15;
        int node = nb + n;
        float4 v = make_float4(0.f, 0.f, 0.f, 0.f);
        if (node < NN) {
            v = reinterpret_cast<const float4*>(g_agg1)[node * 16 + k4];
            float in_n = g_innorm[node];
            float on   = g_outnorm[node];
            float4 bb  = reinterpret_cast<const float4*>(b1)[k4];
            v.x = fmaxf(fmaf(v.x, in_n, bb.x), 0.f) * on;
            v.y = fmaxf(fmaf(v.y, in_n, bb.y), 0.f) * on;
            v.z = fmaxf(fmaf(v.z, in_n, bb.z), 0.f) * on;
            v.w = fmaxf(fmaf(v.w, in_n, bb.w), 0.f) * on;
        }
        xs[k4 * 4 + 0][n] = v.x;
        xs[k4 * 4 + 1][n] = v.y;
        xs[k4 * 4 + 2][n] = v.z;
        xs[k4 * 4 + 3][n] = v.w;
    }
    __syncthreads();

    int tx = tid & 7;
    int ty = tid >> 3;
    float acc[2][4] = {};
    #pragma unroll
    for (int k = 0; k < 64; k++) {
        float4 wv = *reinterpret_cast<const float4*>(&Ws[k * 32 + tx * 4]);
        float x0 = xs[k][ty * 2 + 0];
        float x1 = xs[k][ty * 2 + 1];
        acc[0][0] += x0 * wv.x; acc[0][1] += x0 * wv.y;
        acc[0][2] += x0 * wv.z; acc[0][3] += x0 * wv.w;
        acc[1][0] += x1 * wv.x; acc[1][1] += x1 * wv.y;
        acc[1][2] += x1 * wv.z; acc[1][3] += x1 * wv.w;
    }
    #pragma unroll
    for (int i = 0; i < 2; i++) {
        int node = nb + ty * 2 + i;
        if (node < NN) {
            float4 o = make_float4(acc[i][0], acc[i][1], acc[i][2], acc[i][3]);
            reinterpret_cast<float4*>(g_h2)[node * 8 + tx] = o;
        }
    }
}

// ---- gather2 + final epilogue: warp/node scalar loads ----
__global__ __launch_bounds__(256) void k_gather2(const float* __restrict__ b2,
                                                 float* __restrict__ out) {
    int w = (blockIdx.x * blockDim.x + threadIdx.x) >> 5;
    int lane = threadIdx.x & 31;
    if (w >= NN) return;
    int beg = g_rowptr[w], end = g_rowend[w];

    float a0 = 0.f, a1 = 0.f, a2 = 0.f, a3 = 0.f;
    for (int c = beg; c < end; c += 32) {
        int idx = c + lane;
        int sreg = (idx < end) ? g_csr_src[idx] : 0;
        int n = end - c; if (n > 32) n = 32;
        int j = 0;
        for (; j + 4 <= n; j += 4) {
            int s0 = __shfl_sync(0xffffffffu, sreg, j + 0);
            int s1 = __shfl_sync(0xffffffffu, sreg, j + 1);
            int s2 = __shfl_sync(0xffffffffu, sreg, j + 2);
            int s3 = __shfl_sync(0xffffffffu, sreg, j + 3);
            a0 += g_h2[s0 * 32 + lane];
            a1 += g_h2[s1 * 32 + lane];
            a2 += g_h2[s2 * 32 + lane];
            a3 += g_h2[s3 * 32 + lane];
        }
        for (; j < n; j++) {
            int s = __shfl_sync(0xffffffffu, sreg, j);
            a0 += g_h2[s * 32 + lane];
        }
    }
    float acc = (a0 + a1) + (a2 + a3);
    out[w * 32 + lane] = fmaf(acc, g_innorm[w], b2[lane]);
}

extern "C" void kernel_launch(void* const* d_in, const int* in_sizes, int n_in,
                              void* d_out, int out_size) {
    const float* x   = (const float*)d_in[0];
    const int*   src = (const int*)  d_in[1];
    const int*   dst = (const int*)  d_in[2];
    const float* W1  = (const float*)d_in[3];
    const float* b1  = (const float*)d_in[4];
    const float* W2  = (const float*)d_in[5];
    const float* b2  = (const float*)d_in[6];
    float* out = (float*)d_out;

    const int T = 256;
    k_zero     <<<(NN + T - 1) / T, T>>>();
    k_deg_gemm <<<NBLK_FUSED, 256>>>(src, dst, x, W1);
    k_scanalloc<<<(NN + 255) / 256, 256>>>();
    k_scatter4 <<<(NE / 4 + T - 1) / T, T>>>(src, dst);
    k_gather1  <<<(NN * 32 + 255) / 256, 256>>>();
    k_gemm2    <<<(NN + 63) / 64, 256>>>(W2, b1);
    k_gather2  <<<(NN * 32 + 255) / 256, 256>>>(b2, out);
}